// round 12
// baseline (speedup 1.0000x reference)
#include <cuda_runtime.h>

typedef unsigned long long u64;

#define BLK   384
#define TROWS 256   // rows per block (2 per thread, 128 threads per role)
#define XSTR  257   // padded float stride for transposed x tile

#define OFF_S0 0        // 136*16 symmetric w0  (scaled a2)
#define OFF_S2 2176     // 136*16 symmetric w2  (scaled a2/sqrt3)
#define OFF_S4 4352     // 136*16 symmetric w4  (scaled a1; m-scales in epilogue)
#define OFF_A3 6528     // 120*16 antisym  w3   (scaled a1/sqrt2)
#define OFF_W1 8448     // 256*16 w1            (scaled a1)
#define W_TOTAL 12544
#define SMEM_FLOATS (W_TOTAL + 64 * XSTR)
#define SMEM_BYTES  (SMEM_FLOATS * 4)

#define A1F    0.0625f
#define A2F    0.04419417382415922f
#define A2_3F  0.02551551815399144f
#define A1S2F  0.04419417382415922f
#define S2F    0.7071067811865476f
#define IS6F   0.4082482904638630f

__device__ float g_ws[W_TOTAL];

__global__ void prep_kernel(const float* __restrict__ w0, const float* __restrict__ w1,
                            const float* __restrict__ w2, const float* __restrict__ w3,
                            const float* __restrict__ w4)
{
    int idx = blockIdx.x * blockDim.x + threadIdx.x;
    if (idx >= 4096) return;
    int w = idx & 15;
    int v = (idx >> 4) & 15;
    int u = idx >> 8;
    int sidx = ((v * 16 + u) << 4) + w;

    g_ws[OFF_W1 + idx] = A1F * w1[idx];

    if (u <= v) {
        int p = u * 16 - (u * (u - 1)) / 2 + (v - u);
        float f0 = (u == v) ? w0[idx] : (w0[idx] + w0[sidx]);
        float f2 = (u == v) ? w2[idx] : (w2[idx] + w2[sidx]);
        float f4 = (u == v) ? w4[idx] : (w4[idx] + w4[sidx]);
        g_ws[OFF_S0 + p * 16 + w] = A2F   * f0;
        g_ws[OFF_S2 + p * 16 + w] = A2_3F * f2;
        g_ws[OFF_S4 + p * 16 + w] = A1F   * f4;
    }
    if (u < v) {
        int pa = 15 * u - (u * (u - 1)) / 2 + (v - u - 1);
        g_ws[OFF_A3 + pa * 16 + w] = A1S2F * (w3[idx] - w3[sidx]);
    }
}

// ---- packed fp32 helpers -------------------------------------------------
__device__ __forceinline__ u64 dup2(float s)
{
    unsigned int b = __float_as_uint(s);
    u64 r;
    asm("mov.b64 %0, {%1, %1};" : "=l"(r) : "r"(b));
    return r;
}
__device__ __forceinline__ void fma2(u64& d, u64 a, u64 b)
{
    asm("fma.rn.f32x2 %0, %1, %2, %0;" : "+l"(d) : "l"(a), "l"(b));
}
__device__ __forceinline__ u64 mul2(u64 a, u64 b)
{
    u64 d;
    asm("mul.rn.f32x2 %0, %1, %2;" : "=l"(d) : "l"(a), "l"(b));
    return d;
}
__device__ __forceinline__ void unpk(u64 v, float& lo, float& hi)
{
    unsigned int l, h;
    asm("mov.b64 {%0, %1}, %2;" : "=r"(l), "=r"(h) : "l"(v));
    lo = __uint_as_float(l);
    hi = __uint_as_float(h);
}

// ---- dual-row axpy over one 16-float weight row --------------------------
__device__ __forceinline__ void axpy16_2(u64* aA, u64* aB, const float* wb, u64 fA, u64 fB)
{
    const ulonglong2* wr = reinterpret_cast<const ulonglong2*>(wb);
#pragma unroll
    for (int q = 0; q < 4; q++) {
        ulonglong2 wv = wr[q];
        fma2(aA[2 * q], fA, wv.x); fma2(aA[2 * q + 1], fA, wv.y);
        fma2(aB[2 * q], fB, wv.x); fma2(aB[2 * q + 1], fB, wv.y);
    }
}
__device__ __forceinline__ void axpy16x2_2(u64* aA, u64* aB, const float* wb,
                                           const u64* fA, const u64* fB)
{
    const ulonglong2* wr = reinterpret_cast<const ulonglong2*>(wb);
#pragma unroll
    for (int q = 0; q < 4; q++) {
        ulonglong2 wv = wr[q];
#pragma unroll
        for (int m = 0; m < 2; m++) {
            fma2(aA[8 * m + 2 * q], fA[m], wv.x); fma2(aA[8 * m + 2 * q + 1], fA[m], wv.y);
            fma2(aB[8 * m + 2 * q], fB[m], wv.x); fma2(aB[8 * m + 2 * q + 1], fB[m], wv.y);
        }
    }
}
__device__ __forceinline__ void axpy16x3_2(u64* aA, u64* aB, const float* wb,
                                           const u64* fA, const u64* fB)
{
    const ulonglong2* wr = reinterpret_cast<const ulonglong2*>(wb);
#pragma unroll
    for (int q = 0; q < 4; q++) {
        ulonglong2 wv = wr[q];
#pragma unroll
        for (int m = 0; m < 3; m++) {
            fma2(aA[8 * m + 2 * q], fA[m], wv.x); fma2(aA[8 * m + 2 * q + 1], fA[m], wv.y);
            fma2(aB[8 * m + 2 * q], fB[m], wv.x); fma2(aB[8 * m + 2 * q + 1], fB[m], wv.y);
        }
    }
}

// ---- strided component store: acc[8] -> o[base + stride*w + moff], scaled --
__device__ __forceinline__ void store_comp(const u64* acc, float* o, int base,
                                           int stride, int moff, float sc)
{
#pragma unroll
    for (int j = 0; j < 8; j++) {
        float lo, hi; unpk(acc[j], lo, hi);
        o[base + stride * (2 * j)     + moff] = lo * sc;
        o[base + stride * (2 * j + 1) + moff] = hi * sc;
    }
}

// ---- path1 (0e x 1o -> 1o), factorized, NH u64 (=2*NH w-channels) --------
template<int NH>
__device__ __forceinline__ void path1_run(const float* ws, const float* xr,
                                          float* oA, float* oB, bool vB, int woff)
{
    u64 a0A[16], a0B[16];
#pragma unroll
    for (int u = 0; u < 16; u++) {
        a0A[u] = dup2(xr[u * XSTR]);
        a0B[u] = dup2(xr[u * XSTR + 128]);
    }
    u64 pA[3 * NH], pB[3 * NH];
#pragma unroll
    for (int k = 0; k < 3 * NH; k++) { pA[k] = 0ULL; pB[k] = 0ULL; }

    const float* w1b = ws + OFF_W1 + woff;

    for (int v = 0; v < 16; v++) {
        u64 TA[NH], TB[NH];
        {
            const ulonglong2* wr = reinterpret_cast<const ulonglong2*>(w1b + v * 16);
#pragma unroll
            for (int t = 0; t < NH / 2; t++) {
                ulonglong2 wv = wr[t];
                TA[2 * t] = mul2(a0A[0], wv.x); TA[2 * t + 1] = mul2(a0A[0], wv.y);
                TB[2 * t] = mul2(a0B[0], wv.x); TB[2 * t + 1] = mul2(a0B[0], wv.y);
            }
        }
#pragma unroll
        for (int u = 1; u < 16; u++) {
            const ulonglong2* wr =
                reinterpret_cast<const ulonglong2*>(w1b + u * 256 + v * 16);
#pragma unroll
            for (int t = 0; t < NH / 2; t++) {
                ulonglong2 wv = wr[t];
                fma2(TA[2 * t], a0A[u], wv.x); fma2(TA[2 * t + 1], a0A[u], wv.y);
                fma2(TB[2 * t], a0B[u], wv.x); fma2(TB[2 * t + 1], a0B[u], wv.y);
            }
        }
        const float* fv = xr + (16 + 3 * v) * XSTR;
        u64 xdA = dup2(fv[0]),   ydA = dup2(fv[XSTR]),       zdA = dup2(fv[2 * XSTR]);
        u64 xdB = dup2(fv[128]), ydB = dup2(fv[XSTR + 128]), zdB = dup2(fv[2 * XSTR + 128]);
#pragma unroll
        for (int h = 0; h < NH; h++) {
            fma2(pA[h], TA[h], xdA); fma2(pA[NH + h], TA[h], ydA); fma2(pA[2 * NH + h], TA[h], zdA);
            fma2(pB[h], TB[h], xdB); fma2(pB[NH + h], TB[h], ydB); fma2(pB[2 * NH + h], TB[h], zdB);
        }
    }
#pragma unroll
    for (int m = 0; m < 3; m++)
#pragma unroll
        for (int h = 0; h < NH; h++) {
            float lo, hi; unpk(pA[m * NH + h], lo, hi);
            oA[16 + 3 * (woff + 2 * h)     + m] = lo;
            oA[16 + 3 * (woff + 2 * h + 1) + m] = hi;
            if (vB) {
                unpk(pB[m * NH + h], lo, hi);
                oB[16 + 3 * (woff + 2 * h)     + m] = lo;
                oB[16 + 3 * (woff + 2 * h + 1) + m] = hi;
            }
        }
}

// ---------------------------------------------------------------------------
// 384 threads, 3 roles x 128 threads, 2 rows per thread (r and r+128).
//   role0: o_2e m{0,1,2}          + path1 w8..11
//   role1: o_2e m{3,4} + o_1e m0  + path1 w0..7
//   role2: o_0e + o_1e m{1,2}     + path1 w12..15
// Warp w sits on SMSP w%4 -> each SMSP hosts one warp of every role.
// ---------------------------------------------------------------------------
__global__ __launch_bounds__(BLK, 1)
void tsq_kernel(const float* __restrict__ x, float* __restrict__ out, int n)
{
    extern __shared__ float smem[];
    float* ws = smem;
    float* xs = smem + W_TOTAL;
    int tid = threadIdx.x;

    {
        const float4* gw = reinterpret_cast<const float4*>(g_ws);
        float4* sw = reinterpret_cast<float4*>(ws);
        for (int i = tid; i < W_TOTAL / 4; i += BLK) sw[i] = gw[i];
    }
    int row0 = blockIdx.x * TROWS;
    {
        const float4* x4 = reinterpret_cast<const float4*>(x);
        for (int lin = tid; lin < TROWS * 16; lin += BLK) {
            int rr = lin >> 4, c = lin & 15;
            float4 val = make_float4(0.f, 0.f, 0.f, 0.f);
            if (row0 + rr < n) val = x4[(size_t)(row0 + rr) * 16 + c];
            xs[(4 * c + 0) * XSTR + rr] = val.x;
            xs[(4 * c + 1) * XSTR + rr] = val.y;
            xs[(4 * c + 2) * XSTR + rr] = val.z;
            xs[(4 * c + 3) * XSTR + rr] = val.w;
        }
    }
    __syncthreads();

    int role = tid >> 7;          // 0,1,2 — warp-uniform
    int r    = tid & 127;
    int zA = row0 + r;
    if (zA >= n) return;
    int zB = zA + 128;
    bool vB = (zB < n);
    float* oA = out + (size_t)zA * 192;
    float* oB = out + (size_t)zB * 192;
    const float* xr = xs + r;

    if (role == 0) {
        // ===== o_2e m{0:xy, 1:yz, 2:3z^2-r^2}
        u64 aA[24], aB[24];
#pragma unroll
        for (int k = 0; k < 24; k++) { aA[k] = 0ULL; aB[k] = 0ULL; }
        const float* s4r = ws + OFF_S4;

        for (int u = 0; u < 16; u++) {
            const float* fu = xr + (16 + 3 * u) * XSTR;
            float axA = fu[0],   ayA = fu[XSTR],       azA = fu[2 * XSTR];
            float axB = fu[128], ayB = fu[XSTR + 128], azB = fu[2 * XSTR + 128];
            {   // diagonal
                u64 qA[3], qB[3];
                {
                    float t0 = axA * ayA, t1 = ayA * azA;
                    float pxx = axA * axA, pyy = ayA * ayA, pzz = azA * azA;
                    qA[0] = dup2(t0 + t0); qA[1] = dup2(t1 + t1);
                    float s = pxx + pyy; qA[2] = dup2(fmaf(2.f, pzz, -s));
                }
                {
                    float t0 = axB * ayB, t1 = ayB * azB;
                    float pxx = axB * axB, pyy = ayB * ayB, pzz = azB * azB;
                    qB[0] = dup2(t0 + t0); qB[1] = dup2(t1 + t1);
                    float s = pxx + pyy; qB[2] = dup2(fmaf(2.f, pzz, -s));
                }
                axpy16x3_2(aA, aB, s4r, qA, qB); s4r += 16;
            }
            for (int v = u + 1; v < 16; v++) {
                const float* fv = xr + (16 + 3 * v) * XSTR;
                float bxA = fv[0],   byA = fv[XSTR],       bzA = fv[2 * XSTR];
                float bxB = fv[128], byB = fv[XSTR + 128], bzB = fv[2 * XSTR + 128];
                u64 qA[3], qB[3];
                {
                    float pxx = axA * bxA, pyy = ayA * byA, pzz = azA * bzA;
                    qA[0] = dup2(fmaf(axA, byA, ayA * bxA));
                    qA[1] = dup2(fmaf(ayA, bzA, azA * byA));
                    float s = pxx + pyy; qA[2] = dup2(fmaf(2.f, pzz, -s));
                }
                {
                    float pxx = axB * bxB, pyy = ayB * byB, pzz = azB * bzB;
                    qB[0] = dup2(fmaf(axB, byB, ayB * bxB));
                    qB[1] = dup2(fmaf(ayB, bzB, azB * byB));
                    float s = pxx + pyy; qB[2] = dup2(fmaf(2.f, pzz, -s));
                }
                axpy16x3_2(aA, aB, s4r, qA, qB); s4r += 16;
            }
        }
        store_comp(aA,      oA, 112, 5, 0, S2F);
        store_comp(aA + 8,  oA, 112, 5, 1, S2F);
        store_comp(aA + 16, oA, 112, 5, 2, IS6F);
        if (vB) {
            store_comp(aB,      oB, 112, 5, 0, S2F);
            store_comp(aB + 8,  oB, 112, 5, 1, S2F);
            store_comp(aB + 16, oB, 112, 5, 2, IS6F);
        }
        path1_run<2>(ws, xr, oA, oB, vB, 8);
    } else if (role == 1) {
        // ===== o_2e m{3:xz, 4:x^2-y^2}  +  o_1e m0 (cx)
        u64 aA[16], aB[16], eA[8], eB[8];
#pragma unroll
        for (int k = 0; k < 16; k++) { aA[k] = 0ULL; aB[k] = 0ULL; }
#pragma unroll
        for (int k = 0; k < 8; k++)  { eA[k] = 0ULL; eB[k] = 0ULL; }
        const float* s4r = ws + OFF_S4;
        const float* a3r = ws + OFF_A3;

        for (int u = 0; u < 16; u++) {
            const float* fu = xr + (16 + 3 * u) * XSTR;
            float axA = fu[0],   ayA = fu[XSTR],       azA = fu[2 * XSTR];
            float axB = fu[128], ayB = fu[XSTR + 128], azB = fu[2 * XSTR + 128];
            {   // diagonal (no cross)
                u64 qA[2], qB[2];
                {
                    float t = axA * azA;
                    float pxx = axA * axA, pyy = ayA * ayA;
                    qA[0] = dup2(t + t); qA[1] = dup2(pxx - pyy);
                }
                {
                    float t = axB * azB;
                    float pxx = axB * axB, pyy = ayB * ayB;
                    qB[0] = dup2(t + t); qB[1] = dup2(pxx - pyy);
                }
                axpy16x2_2(aA, aB, s4r, qA, qB); s4r += 16;
            }
            for (int v = u + 1; v < 16; v++) {
                const float* fv = xr + (16 + 3 * v) * XSTR;
                float bxA = fv[0],   byA = fv[XSTR],       bzA = fv[2 * XSTR];
                float bxB = fv[128], byB = fv[XSTR + 128], bzB = fv[2 * XSTR + 128];
                u64 qA[2], qB[2], cxA, cxB;
                {
                    float pxx = axA * bxA, pyy = ayA * byA;
                    qA[0] = dup2(fmaf(axA, bzA, azA * bxA));
                    qA[1] = dup2(pxx - pyy);
                    cxA   = dup2(fmaf(ayA, bzA, -(azA * byA)));
                }
                {
                    float pxx = axB * bxB, pyy = ayB * byB;
                    qB[0] = dup2(fmaf(axB, bzB, azB * bxB));
                    qB[1] = dup2(pxx - pyy);
                    cxB   = dup2(fmaf(ayB, bzB, -(azB * byB)));
                }
                axpy16x2_2(aA, aB, s4r, qA, qB);  s4r += 16;
                axpy16_2(eA, eB, a3r, cxA, cxB);  a3r += 16;
            }
        }
        store_comp(aA,     oA, 112, 5, 3, S2F);
        store_comp(aA + 8, oA, 112, 5, 4, S2F);
        store_comp(eA,     oA, 64,  3, 0, 1.0f);
        if (vB) {
            store_comp(aB,     oB, 112, 5, 3, S2F);
            store_comp(aB + 8, oB, 112, 5, 4, S2F);
            store_comp(eB,     oB, 64,  3, 0, 1.0f);
        }
        path1_run<4>(ws, xr, oA, oB, vB, 0);
    } else {
        // ===== o_0e (paths 0+2)  +  o_1e m{1:cy, 2:cz}
        u64 cA[8], cB[8], eA[16], eB[16];
#pragma unroll
        for (int k = 0; k < 8; k++)  { cA[k] = 0ULL; cB[k] = 0ULL; }
#pragma unroll
        for (int k = 0; k < 16; k++) { eA[k] = 0ULL; eB[k] = 0ULL; }
        const float* s0r = ws + OFF_S0;
        const float* s2r = ws + OFF_S2;
        const float* a3r = ws + OFF_A3;

        for (int u = 0; u < 16; u++) {
            float a0A = xr[u * XSTR], a0B = xr[u * XSTR + 128];
            const float* fu = xr + (16 + 3 * u) * XSTR;
            float axA = fu[0],   ayA = fu[XSTR],       azA = fu[2 * XSTR];
            float axB = fu[128], ayB = fu[XSTR + 128], azB = fu[2 * XSTR + 128];
            {   // diagonal
                float sA = a0A * a0A, sB = a0B * a0B;
                float dA = fmaf(axA, axA, fmaf(ayA, ayA, azA * azA));
                float dB = fmaf(axB, axB, fmaf(ayB, ayB, azB * azB));
                axpy16_2(cA, cB, s0r, dup2(sA), dup2(sB)); s0r += 16;
                axpy16_2(cA, cB, s2r, dup2(dA), dup2(dB)); s2r += 16;
            }
            for (int v = u + 1; v < 16; v++) {
                float b0A = xr[v * XSTR], b0B = xr[v * XSTR + 128];
                const float* fv = xr + (16 + 3 * v) * XSTR;
                float bxA = fv[0],   byA = fv[XSTR],       bzA = fv[2 * XSTR];
                float bxB = fv[128], byB = fv[XSTR + 128], bzB = fv[2 * XSTR + 128];

                float sA = a0A * b0A, sB = a0B * b0B;
                float dA = fmaf(axA, bxA, fmaf(ayA, byA, azA * bzA));
                float dB = fmaf(axB, bxB, fmaf(ayB, byB, azB * bzB));
                u64 gA[2], gB[2];
                gA[0] = dup2(fmaf(azA, bxA, -(axA * bzA)));   // cy
                gA[1] = dup2(fmaf(axA, byA, -(ayA * bxA)));   // cz
                gB[0] = dup2(fmaf(azB, bxB, -(axB * bzB)));
                gB[1] = dup2(fmaf(axB, byB, -(ayB * bxB)));

                axpy16_2(cA, cB, s0r, dup2(sA), dup2(sB)); s0r += 16;
                axpy16_2(cA, cB, s2r, dup2(dA), dup2(dB)); s2r += 16;
                axpy16x2_2(eA, eB, a3r, gA, gB);           a3r += 16;
            }
        }
        {   // o_0e: contiguous, vectorized
            float ob[16];
#pragma unroll
            for (int j = 0; j < 8; j++) unpk(cA[j], ob[2 * j], ob[2 * j + 1]);
            float4* o4 = reinterpret_cast<float4*>(oA);
#pragma unroll
            for (int j = 0; j < 4; j++)
                o4[j] = make_float4(ob[4 * j], ob[4 * j + 1], ob[4 * j + 2], ob[4 * j + 3]);
            if (vB) {
#pragma unroll
                for (int j = 0; j < 8; j++) unpk(cB[j], ob[2 * j], ob[2 * j + 1]);
                float4* p4 = reinterpret_cast<float4*>(oB);
#pragma unroll
                for (int j = 0; j < 4; j++)
                    p4[j] = make_float4(ob[4 * j], ob[4 * j + 1], ob[4 * j + 2], ob[4 * j + 3]);
            }
        }
        store_comp(eA,     oA, 64, 3, 1, 1.0f);
        store_comp(eA + 8, oA, 64, 3, 2, 1.0f);
        if (vB) {
            store_comp(eB,     oB, 64, 3, 1, 1.0f);
            store_comp(eB + 8, oB, 64, 3, 2, 1.0f);
        }
        path1_run<2>(ws, xr, oA, oB, vB, 12);
    }
}

// ---------------------------------------------------------------------------
extern "C" void kernel_launch(void* const* d_in, const int* in_sizes, int n_in,
                              void* d_out, int out_size)
{
    const float* x  = (const float*)d_in[0];
    const float* w0 = (const float*)d_in[1];
    const float* w1 = (const float*)d_in[2];
    const float* w2 = (const float*)d_in[3];
    const float* w3 = (const float*)d_in[4];
    const float* w4 = (const float*)d_in[5];
    float* out = (float*)d_out;
    int n = in_sizes[0] / 64;

    cudaFuncSetAttribute(tsq_kernel, cudaFuncAttributeMaxDynamicSharedMemorySize, SMEM_BYTES);

    prep_kernel<<<16, 256>>>(w0, w1, w2, w3, w4);
    tsq_kernel<<<(n + TROWS - 1) / TROWS, BLK, SMEM_BYTES>>>(x, out, n);
}

// round 13
// speedup vs baseline: 1.0208x; 1.0208x over previous
#include <cuda_runtime.h>

typedef unsigned long long u64;

#define BLK   384
#define TROWS 256   // rows per block (2 per thread, 128 threads per role)
#define XSTR  257   // padded float stride for transposed x tile

#define OFF_S0 0        // 136*16 symmetric w0  (scaled a2)
#define OFF_S2 2176     // 136*16 symmetric w2  (scaled a2/sqrt3)
#define OFF_S4 4352     // 136*16 symmetric w4  (scaled a1; m-scales in epilogue)
#define OFF_A3 6528     // 120*16 antisym  w3   (scaled a1/sqrt2)
#define OFF_W1 8448     // 256*16 w1            (scaled a1)
#define W_TOTAL 12544
#define SMEM_FLOATS (W_TOTAL + 64 * XSTR)
#define SMEM_BYTES  (SMEM_FLOATS * 4)

#define A1F    0.0625f
#define A2F    0.04419417382415922f
#define A2_3F  0.02551551815399144f
#define A1S2F  0.04419417382415922f
#define S2F    0.7071067811865476f
#define IS6F   0.4082482904638630f

__device__ float g_ws[W_TOTAL];

__global__ void prep_kernel(const float* __restrict__ w0, const float* __restrict__ w1,
                            const float* __restrict__ w2, const float* __restrict__ w3,
                            const float* __restrict__ w4)
{
    int idx = blockIdx.x * blockDim.x + threadIdx.x;
    if (idx >= 4096) return;
    int w = idx & 15;
    int v = (idx >> 4) & 15;
    int u = idx >> 8;
    int sidx = ((v * 16 + u) << 4) + w;

    g_ws[OFF_W1 + idx] = A1F * w1[idx];

    if (u <= v) {
        int p = u * 16 - (u * (u - 1)) / 2 + (v - u);
        float f0 = (u == v) ? w0[idx] : (w0[idx] + w0[sidx]);
        float f2 = (u == v) ? w2[idx] : (w2[idx] + w2[sidx]);
        float f4 = (u == v) ? w4[idx] : (w4[idx] + w4[sidx]);
        g_ws[OFF_S0 + p * 16 + w] = A2F   * f0;
        g_ws[OFF_S2 + p * 16 + w] = A2_3F * f2;
        g_ws[OFF_S4 + p * 16 + w] = A1F   * f4;
    }
    if (u < v) {
        int pa = 15 * u - (u * (u - 1)) / 2 + (v - u - 1);
        g_ws[OFF_A3 + pa * 16 + w] = A1S2F * (w3[idx] - w3[sidx]);
    }
}

// ---- packed fp32 helpers -------------------------------------------------
__device__ __forceinline__ u64 dup2(float s)
{
    unsigned int b = __float_as_uint(s);
    u64 r;
    asm("mov.b64 %0, {%1, %1};" : "=l"(r) : "r"(b));
    return r;
}
__device__ __forceinline__ void fma2(u64& d, u64 a, u64 b)
{
    asm("fma.rn.f32x2 %0, %1, %2, %0;" : "+l"(d) : "l"(a), "l"(b));
}
__device__ __forceinline__ u64 mul2(u64 a, u64 b)
{
    u64 d;
    asm("mul.rn.f32x2 %0, %1, %2;" : "=l"(d) : "l"(a), "l"(b));
    return d;
}
__device__ __forceinline__ void unpk(u64 v, float& lo, float& hi)
{
    unsigned int l, h;
    asm("mov.b64 {%0, %1}, %2;" : "=r"(l), "=r"(h) : "l"(v));
    lo = __uint_as_float(l);
    hi = __uint_as_float(h);
}

// ---- dual-row axpy over one 16-float weight row --------------------------
__device__ __forceinline__ void axpy16_2(u64* aA, u64* aB, const float* wb, u64 fA, u64 fB)
{
    const ulonglong2* wr = reinterpret_cast<const ulonglong2*>(wb);
#pragma unroll
    for (int q = 0; q < 4; q++) {
        ulonglong2 wv = wr[q];
        fma2(aA[2 * q], fA, wv.x); fma2(aA[2 * q + 1], fA, wv.y);
        fma2(aB[2 * q], fB, wv.x); fma2(aB[2 * q + 1], fB, wv.y);
    }
}
__device__ __forceinline__ void axpy16x2_2(u64* aA, u64* aB, const float* wb,
                                           const u64* fA, const u64* fB)
{
    const ulonglong2* wr = reinterpret_cast<const ulonglong2*>(wb);
#pragma unroll
    for (int q = 0; q < 4; q++) {
        ulonglong2 wv = wr[q];
#pragma unroll
        for (int m = 0; m < 2; m++) {
            fma2(aA[8 * m + 2 * q], fA[m], wv.x); fma2(aA[8 * m + 2 * q + 1], fA[m], wv.y);
            fma2(aB[8 * m + 2 * q], fB[m], wv.x); fma2(aB[8 * m + 2 * q + 1], fB[m], wv.y);
        }
    }
}
__device__ __forceinline__ void axpy16x3_2(u64* aA, u64* aB, const float* wb,
                                           const u64* fA, const u64* fB)
{
    const ulonglong2* wr = reinterpret_cast<const ulonglong2*>(wb);
#pragma unroll
    for (int q = 0; q < 4; q++) {
        ulonglong2 wv = wr[q];
#pragma unroll
        for (int m = 0; m < 3; m++) {
            fma2(aA[8 * m + 2 * q], fA[m], wv.x); fma2(aA[8 * m + 2 * q + 1], fA[m], wv.y);
            fma2(aB[8 * m + 2 * q], fB[m], wv.x); fma2(aB[8 * m + 2 * q + 1], fB[m], wv.y);
        }
    }
}

// ---- strided component store: acc[8] -> o[base + stride*w + moff], scaled --
__device__ __forceinline__ void store_comp(const u64* acc, float* o, int base,
                                           int stride, int moff, float sc)
{
#pragma unroll
    for (int j = 0; j < 8; j++) {
        float lo, hi; unpk(acc[j], lo, hi);
        o[base + stride * (2 * j)     + moff] = lo * sc;
        o[base + stride * (2 * j + 1) + moff] = hi * sc;
    }
}

// ---- path1 (0e x 1o -> 1o), factorized, NH u64 (=2*NH w-channels) --------
// NOINLINE: firewalls this phase's register allocation from the main loops
// (sequential phases; avoids the R12 spill at the 168-reg cap).
// a0 kept as floats (32 regs, not 64); dup to f32x2 in-loop (ALU pipe, idle).
template<int NH>
__device__ __noinline__ void path1_run(const float* ws, const float* xr,
                                       float* oA, float* oB, bool vB, int woff)
{
    float a0A[16], a0B[16];
#pragma unroll
    for (int u = 0; u < 16; u++) {
        a0A[u] = xr[u * XSTR];
        a0B[u] = xr[u * XSTR + 128];
    }
    u64 pA[3 * NH], pB[3 * NH];
#pragma unroll
    for (int k = 0; k < 3 * NH; k++) { pA[k] = 0ULL; pB[k] = 0ULL; }

    const float* w1b = ws + OFF_W1 + woff;

    for (int v = 0; v < 16; v++) {
        u64 TA[NH], TB[NH];
        {
            u64 dA = dup2(a0A[0]), dB = dup2(a0B[0]);
            const ulonglong2* wr = reinterpret_cast<const ulonglong2*>(w1b + v * 16);
#pragma unroll
            for (int t = 0; t < NH / 2; t++) {
                ulonglong2 wv = wr[t];
                TA[2 * t] = mul2(dA, wv.x); TA[2 * t + 1] = mul2(dA, wv.y);
                TB[2 * t] = mul2(dB, wv.x); TB[2 * t + 1] = mul2(dB, wv.y);
            }
        }
#pragma unroll
        for (int u = 1; u < 16; u++) {
            u64 dA = dup2(a0A[u]), dB = dup2(a0B[u]);
            const ulonglong2* wr =
                reinterpret_cast<const ulonglong2*>(w1b + u * 256 + v * 16);
#pragma unroll
            for (int t = 0; t < NH / 2; t++) {
                ulonglong2 wv = wr[t];
                fma2(TA[2 * t], dA, wv.x); fma2(TA[2 * t + 1], dA, wv.y);
                fma2(TB[2 * t], dB, wv.x); fma2(TB[2 * t + 1], dB, wv.y);
            }
        }
        const float* fv = xr + (16 + 3 * v) * XSTR;
        u64 xdA = dup2(fv[0]),   ydA = dup2(fv[XSTR]),       zdA = dup2(fv[2 * XSTR]);
        u64 xdB = dup2(fv[128]), ydB = dup2(fv[XSTR + 128]), zdB = dup2(fv[2 * XSTR + 128]);
#pragma unroll
        for (int h = 0; h < NH; h++) {
            fma2(pA[h], TA[h], xdA); fma2(pA[NH + h], TA[h], ydA); fma2(pA[2 * NH + h], TA[h], zdA);
            fma2(pB[h], TB[h], xdB); fma2(pB[NH + h], TB[h], ydB); fma2(pB[2 * NH + h], TB[h], zdB);
        }
    }
#pragma unroll
    for (int m = 0; m < 3; m++)
#pragma unroll
        for (int h = 0; h < NH; h++) {
            float lo, hi; unpk(pA[m * NH + h], lo, hi);
            oA[16 + 3 * (woff + 2 * h)     + m] = lo;
            oA[16 + 3 * (woff + 2 * h + 1) + m] = hi;
            if (vB) {
                unpk(pB[m * NH + h], lo, hi);
                oB[16 + 3 * (woff + 2 * h)     + m] = lo;
                oB[16 + 3 * (woff + 2 * h + 1) + m] = hi;
            }
        }
}

// ---------------------------------------------------------------------------
// 384 threads, 3 roles x 128 threads, 2 rows per thread (r and r+128).
//   role0: o_2e m{0,1,2}          + path1 w8..11
//   role1: o_2e m{3,4} + o_1e m0  + path1 w0..7
//   role2: o_0e + o_1e m{1,2}     + path1 w12..15
// Warp w sits on SMSP w%4 -> each SMSP hosts one warp of every role.
// ---------------------------------------------------------------------------
__global__ __launch_bounds__(BLK, 1)
void tsq_kernel(const float* __restrict__ x, float* __restrict__ out, int n)
{
    extern __shared__ float smem[];
    float* ws = smem;
    float* xs = smem + W_TOTAL;
    int tid = threadIdx.x;

    {
        const float4* gw = reinterpret_cast<const float4*>(g_ws);
        float4* sw = reinterpret_cast<float4*>(ws);
        for (int i = tid; i < W_TOTAL / 4; i += BLK) sw[i] = gw[i];
    }
    int row0 = blockIdx.x * TROWS;
    {
        const float4* x4 = reinterpret_cast<const float4*>(x);
        for (int lin = tid; lin < TROWS * 16; lin += BLK) {
            int rr = lin >> 4, c = lin & 15;
            float4 val = make_float4(0.f, 0.f, 0.f, 0.f);
            if (row0 + rr < n) val = x4[(size_t)(row0 + rr) * 16 + c];
            xs[(4 * c + 0) * XSTR + rr] = val.x;
            xs[(4 * c + 1) * XSTR + rr] = val.y;
            xs[(4 * c + 2) * XSTR + rr] = val.z;
            xs[(4 * c + 3) * XSTR + rr] = val.w;
        }
    }
    __syncthreads();

    int role = tid >> 7;          // 0,1,2 — warp-uniform
    int r    = tid & 127;
    int zA = row0 + r;
    if (zA >= n) return;
    int zB = zA + 128;
    bool vB = (zB < n);
    float* oA = out + (size_t)zA * 192;
    float* oB = out + (size_t)zB * 192;
    const float* xr = xs + r;

    if (role == 0) {
        // ===== o_2e m{0:xy, 1:yz, 2:3z^2-r^2}
        u64 aA[24], aB[24];
#pragma unroll
        for (int k = 0; k < 24; k++) { aA[k] = 0ULL; aB[k] = 0ULL; }
        const float* s4r = ws + OFF_S4;

        for (int u = 0; u < 16; u++) {
            const float* fu = xr + (16 + 3 * u) * XSTR;
            float axA = fu[0],   ayA = fu[XSTR],       azA = fu[2 * XSTR];
            float axB = fu[128], ayB = fu[XSTR + 128], azB = fu[2 * XSTR + 128];
            {   // diagonal
                u64 qA[3], qB[3];
                {
                    float t0 = axA * ayA, t1 = ayA * azA;
                    float pxx = axA * axA, pyy = ayA * ayA, pzz = azA * azA;
                    qA[0] = dup2(t0 + t0); qA[1] = dup2(t1 + t1);
                    float s = pxx + pyy; qA[2] = dup2(fmaf(2.f, pzz, -s));
                }
                {
                    float t0 = axB * ayB, t1 = ayB * azB;
                    float pxx = axB * axB, pyy = ayB * ayB, pzz = azB * azB;
                    qB[0] = dup2(t0 + t0); qB[1] = dup2(t1 + t1);
                    float s = pxx + pyy; qB[2] = dup2(fmaf(2.f, pzz, -s));
                }
                axpy16x3_2(aA, aB, s4r, qA, qB); s4r += 16;
            }
            for (int v = u + 1; v < 16; v++) {
                const float* fv = xr + (16 + 3 * v) * XSTR;
                float bxA = fv[0],   byA = fv[XSTR],       bzA = fv[2 * XSTR];
                float bxB = fv[128], byB = fv[XSTR + 128], bzB = fv[2 * XSTR + 128];
                u64 qA[3], qB[3];
                {
                    float pxx = axA * bxA, pyy = ayA * byA, pzz = azA * bzA;
                    qA[0] = dup2(fmaf(axA, byA, ayA * bxA));
                    qA[1] = dup2(fmaf(ayA, bzA, azA * byA));
                    float s = pxx + pyy; qA[2] = dup2(fmaf(2.f, pzz, -s));
                }
                {
                    float pxx = axB * bxB, pyy = ayB * byB, pzz = azB * bzB;
                    qB[0] = dup2(fmaf(axB, byB, ayB * bxB));
                    qB[1] = dup2(fmaf(ayB, bzB, azB * byB));
                    float s = pxx + pyy; qB[2] = dup2(fmaf(2.f, pzz, -s));
                }
                axpy16x3_2(aA, aB, s4r, qA, qB); s4r += 16;
            }
        }
        store_comp(aA,      oA, 112, 5, 0, S2F);
        store_comp(aA + 8,  oA, 112, 5, 1, S2F);
        store_comp(aA + 16, oA, 112, 5, 2, IS6F);
        if (vB) {
            store_comp(aB,      oB, 112, 5, 0, S2F);
            store_comp(aB + 8,  oB, 112, 5, 1, S2F);
            store_comp(aB + 16, oB, 112, 5, 2, IS6F);
        }
        path1_run<2>(ws, xr, oA, oB, vB, 8);
    } else if (role == 1) {
        // ===== o_2e m{3:xz, 4:x^2-y^2}  +  o_1e m0 (cx)
        u64 aA[16], aB[16], eA[8], eB[8];
#pragma unroll
        for (int k = 0; k < 16; k++) { aA[k] = 0ULL; aB[k] = 0ULL; }
#pragma unroll
        for (int k = 0; k < 8; k++)  { eA[k] = 0ULL; eB[k] = 0ULL; }
        const float* s4r = ws + OFF_S4;
        const float* a3r = ws + OFF_A3;

        for (int u = 0; u < 16; u++) {
            const float* fu = xr + (16 + 3 * u) * XSTR;
            float axA = fu[0],   ayA = fu[XSTR],       azA = fu[2 * XSTR];
            float axB = fu[128], ayB = fu[XSTR + 128], azB = fu[2 * XSTR + 128];
            {   // diagonal (no cross)
                u64 qA[2], qB[2];
                {
                    float t = axA * azA;
                    float pxx = axA * axA, pyy = ayA * ayA;
                    qA[0] = dup2(t + t); qA[1] = dup2(pxx - pyy);
                }
                {
                    float t = axB * azB;
                    float pxx = axB * axB, pyy = ayB * ayB;
                    qB[0] = dup2(t + t); qB[1] = dup2(pxx - pyy);
                }
                axpy16x2_2(aA, aB, s4r, qA, qB); s4r += 16;
            }
            for (int v = u + 1; v < 16; v++) {
                const float* fv = xr + (16 + 3 * v) * XSTR;
                float bxA = fv[0],   byA = fv[XSTR],       bzA = fv[2 * XSTR];
                float bxB = fv[128], byB = fv[XSTR + 128], bzB = fv[2 * XSTR + 128];
                u64 qA[2], qB[2], cxA, cxB;
                {
                    float pxx = axA * bxA, pyy = ayA * byA;
                    qA[0] = dup2(fmaf(axA, bzA, azA * bxA));
                    qA[1] = dup2(pxx - pyy);
                    cxA   = dup2(fmaf(ayA, bzA, -(azA * byA)));
                }
                {
                    float pxx = axB * bxB, pyy = ayB * byB;
                    qB[0] = dup2(fmaf(axB, bzB, azB * bxB));
                    qB[1] = dup2(pxx - pyy);
                    cxB   = dup2(fmaf(ayB, bzB, -(azB * byB)));
                }
                axpy16x2_2(aA, aB, s4r, qA, qB);  s4r += 16;
                axpy16_2(eA, eB, a3r, cxA, cxB);  a3r += 16;
            }
        }
        store_comp(aA,     oA, 112, 5, 3, S2F);
        store_comp(aA + 8, oA, 112, 5, 4, S2F);
        store_comp(eA,     oA, 64,  3, 0, 1.0f);
        if (vB) {
            store_comp(aB,     oB, 112, 5, 3, S2F);
            store_comp(aB + 8, oB, 112, 5, 4, S2F);
            store_comp(eB,     oB, 64,  3, 0, 1.0f);
        }
        path1_run<4>(ws, xr, oA, oB, vB, 0);
    } else {
        // ===== o_0e (paths 0+2)  +  o_1e m{1:cy, 2:cz}
        u64 cA[8], cB[8], eA[16], eB[16];
#pragma unroll
        for (int k = 0; k < 8; k++)  { cA[k] = 0ULL; cB[k] = 0ULL; }
#pragma unroll
        for (int k = 0; k < 16; k++) { eA[k] = 0ULL; eB[k] = 0ULL; }
        const float* s0r = ws + OFF_S0;
        const float* s2r = ws + OFF_S2;
        const float* a3r = ws + OFF_A3;

        for (int u = 0; u < 16; u++) {
            float a0A = xr[u * XSTR], a0B = xr[u * XSTR + 128];
            const float* fu = xr + (16 + 3 * u) * XSTR;
            float axA = fu[0],   ayA = fu[XSTR],       azA = fu[2 * XSTR];
            float axB = fu[128], ayB = fu[XSTR + 128], azB = fu[2 * XSTR + 128];
            {   // diagonal
                float sA = a0A * a0A, sB = a0B * a0B;
                float dA = fmaf(axA, axA, fmaf(ayA, ayA, azA * azA));
                float dB = fmaf(axB, axB, fmaf(ayB, ayB, azB * azB));
                axpy16_2(cA, cB, s0r, dup2(sA), dup2(sB)); s0r += 16;
                axpy16_2(cA, cB, s2r, dup2(dA), dup2(dB)); s2r += 16;
            }
            for (int v = u + 1; v < 16; v++) {
                float b0A = xr[v * XSTR], b0B = xr[v * XSTR + 128];
                const float* fv = xr + (16 + 3 * v) * XSTR;
                float bxA = fv[0],   byA = fv[XSTR],       bzA = fv[2 * XSTR];
                float bxB = fv[128], byB = fv[XSTR + 128], bzB = fv[2 * XSTR + 128];

                float sA = a0A * b0A, sB = a0B * b0B;
                float dA = fmaf(axA, bxA, fmaf(ayA, byA, azA * bzA));
                float dB = fmaf(axB, bxB, fmaf(ayB, byB, azB * bzB));
                u64 gA[2], gB[2];
                gA[0] = dup2(fmaf(azA, bxA, -(axA * bzA)));   // cy
                gA[1] = dup2(fmaf(axA, byA, -(ayA * bxA)));   // cz
                gB[0] = dup2(fmaf(azB, bxB, -(axB * bzB)));
                gB[1] = dup2(fmaf(axB, byB, -(ayB * bxB)));

                axpy16_2(cA, cB, s0r, dup2(sA), dup2(sB)); s0r += 16;
                axpy16_2(cA, cB, s2r, dup2(dA), dup2(dB)); s2r += 16;
                axpy16x2_2(eA, eB, a3r, gA, gB);           a3r += 16;
            }
        }
        {   // o_0e: contiguous, vectorized
            float ob[16];
#pragma unroll
            for (int j = 0; j < 8; j++) unpk(cA[j], ob[2 * j], ob[2 * j + 1]);
            float4* o4 = reinterpret_cast<float4*>(oA);
#pragma unroll
            for (int j = 0; j < 4; j++)
                o4[j] = make_float4(ob[4 * j], ob[4 * j + 1], ob[4 * j + 2], ob[4 * j + 3]);
            if (vB) {
#pragma unroll
                for (int j = 0; j < 8; j++) unpk(cB[j], ob[2 * j], ob[2 * j + 1]);
                float4* p4 = reinterpret_cast<float4*>(oB);
#pragma unroll
                for (int j = 0; j < 4; j++)
                    p4[j] = make_float4(ob[4 * j], ob[4 * j + 1], ob[4 * j + 2], ob[4 * j + 3]);
            }
        }
        store_comp(eA,     oA, 64, 3, 1, 1.0f);
        store_comp(eA + 8, oA, 64, 3, 2, 1.0f);
        if (vB) {
            store_comp(eB,     oB, 64, 3, 1, 1.0f);
            store_comp(eB + 8, oB, 64, 3, 2, 1.0f);
        }
        path1_run<2>(ws, xr, oA, oB, vB, 12);
    }
}

// ---------------------------------------------------------------------------
extern "C" void kernel_launch(void* const* d_in, const int* in_sizes, int n_in,
                              void* d_out, int out_size)
{
    const float* x  = (const float*)d_in[0];
    const float* w0 = (const float*)d_in[1];
    const float* w1 = (const float*)d_in[2];
    const float* w2 = (const float*)d_in[3];
    const float* w3 = (const float*)d_in[4];
    const float* w4 = (const float*)d_in[5];
    float* out = (float*)d_out;
    int n = in_sizes[0] / 64;

    cudaFuncSetAttribute(tsq_kernel, cudaFuncAttributeMaxDynamicSharedMemorySize, SMEM_BYTES);

    prep_kernel<<<16, 256>>>(w0, w1, w2, w3, w4);
    tsq_kernel<<<(n + TROWS - 1) / TROWS, BLK, SMEM_BYTES>>>(x, out, n);
}